// round 1
// baseline (speedup 1.0000x reference)
#include <cuda_runtime.h>

// Biquad DF2T, B=512 channels, T=48000 samples.
// Chunked parallel-in-time: state s=(z1,z2), s' = A s + u(x), A=[[-a1,1],[-a2,0]]
// constant per channel => chunk end-state = A^L * s_start + p_chunk(zero-init).

#define NB 512
#define NT 48000
#define NK 240            // chunks per channel
#define NL 200            // samples per chunk (NK*NL == NT), divisible by 4

static_assert(NK * NL == NT, "chunking must cover T exactly");

// scratch (no allocations allowed -> device globals)
__device__ float2 g_p[NB * NK];   // zero-init final state per chunk
__device__ float2 g_s[NB * NK];   // true starting state per chunk

// one recurrence step (state update only)
#define STEP_STATE(xv)                          \
    do {                                        \
        float t_   = fmaf(c1, (xv), z2);        \
        float nz1_ = fmaf(-a1, z1, t_);         \
        z2 = fmaf(-a2, z1, c2 * (xv));          \
        z1 = nz1_;                              \
    } while (0)

// ---------------------------------------------------------------------------
// Pass 1: per (channel, chunk) run from zero state, keep only final state.
// ---------------------------------------------------------------------------
__global__ void __launch_bounds__(256)
biquad_pass1(const float* __restrict__ x,
             const float* __restrict__ b0v, const float* __restrict__ b1v,
             const float* __restrict__ b2v, const float* __restrict__ a1v,
             const float* __restrict__ a2v)
{
    int tid = blockIdx.x * blockDim.x + threadIdx.x;
    if (tid >= NB * NK) return;
    int ch = tid / NK;
    int k  = tid % NK;

    float a1 = a1v[ch], a2 = a2v[ch], b0 = b0v[ch];
    float c1 = fmaf(-a1, b0, b1v[ch]);   // b1 - a1*b0
    float c2 = fmaf(-a2, b0, b2v[ch]);   // b2 - a2*b0

    const float4* xp =
        reinterpret_cast<const float4*>(x + (size_t)ch * NT + (size_t)k * NL);

    float z1 = 0.f, z2 = 0.f;
    #pragma unroll 2
    for (int i = 0; i < NL / 4; i++) {
        float4 v = xp[i];
        STEP_STATE(v.x);
        STEP_STATE(v.y);
        STEP_STATE(v.z);
        STEP_STATE(v.w);
    }
    g_p[tid] = make_float2(z1, z2);
}

// ---------------------------------------------------------------------------
// Pass 2: one thread per channel. M = A^NL by binary powering, then the
// sequential K-chunk state fixup: s_{k+1} = M * s_k + p_k.
// ---------------------------------------------------------------------------
__global__ void __launch_bounds__(NB)
biquad_pass2(const float* __restrict__ a1v, const float* __restrict__ a2v)
{
    int ch = threadIdx.x;            // <<<1, 512>>>
    float a1 = a1v[ch], a2 = a2v[ch];

    // A = [[-a1, 1], [-a2, 0]]
    float m00 = -a1, m01 = 1.f, m10 = -a2, m11 = 0.f;
    float r00 = 1.f, r01 = 0.f, r10 = 0.f, r11 = 1.f;
    int e = NL;
    while (e) {
        if (e & 1) {
            float t00 = r00 * m00 + r01 * m10;
            float t01 = r00 * m01 + r01 * m11;
            float t10 = r10 * m00 + r11 * m10;
            float t11 = r10 * m01 + r11 * m11;
            r00 = t00; r01 = t01; r10 = t10; r11 = t11;
        }
        e >>= 1;
        if (e) {
            float t00 = m00 * m00 + m01 * m10;
            float t01 = m00 * m01 + m01 * m11;
            float t10 = m10 * m00 + m11 * m10;
            float t11 = m10 * m01 + m11 * m11;
            m00 = t00; m01 = t01; m10 = t10; m11 = t11;
        }
    }

    float z1 = 0.f, z2 = 0.f;
    int base = ch * NK;
    #pragma unroll 4
    for (int k = 0; k < NK; k++) {
        g_s[base + k] = make_float2(z1, z2);
        float2 p = g_p[base + k];
        float nz1 = fmaf(r00, z1, fmaf(r01, z2, p.x));
        float nz2 = fmaf(r10, z1, fmaf(r11, z2, p.y));
        z1 = nz1; z2 = nz2;
    }
}

// ---------------------------------------------------------------------------
// Pass 3: per (channel, chunk) run from the true starting state, write y.
// ---------------------------------------------------------------------------
__global__ void __launch_bounds__(256)
biquad_pass3(const float* __restrict__ x, float* __restrict__ y,
             const float* __restrict__ b0v, const float* __restrict__ b1v,
             const float* __restrict__ b2v, const float* __restrict__ a1v,
             const float* __restrict__ a2v)
{
    int tid = blockIdx.x * blockDim.x + threadIdx.x;
    if (tid >= NB * NK) return;
    int ch = tid / NK;
    int k  = tid % NK;

    float a1 = a1v[ch], a2 = a2v[ch], b0 = b0v[ch];
    float c1 = fmaf(-a1, b0, b1v[ch]);
    float c2 = fmaf(-a2, b0, b2v[ch]);

    size_t off = (size_t)ch * NT + (size_t)k * NL;
    const float4* xp = reinterpret_cast<const float4*>(x + off);
    float4*       yp = reinterpret_cast<float4*>(y + off);

    float2 s0 = g_s[tid];
    float z1 = s0.x, z2 = s0.y;

    #pragma unroll 2
    for (int i = 0; i < NL / 4; i++) {
        float4 v = xp[i];
        float4 o;
        o.x = fmaf(b0, v.x, z1); STEP_STATE(v.x);
        o.y = fmaf(b0, v.y, z1); STEP_STATE(v.y);
        o.z = fmaf(b0, v.z, z1); STEP_STATE(v.z);
        o.w = fmaf(b0, v.w, z1); STEP_STATE(v.w);
        yp[i] = o;
    }
}

// ---------------------------------------------------------------------------
extern "C" void kernel_launch(void* const* d_in, const int* in_sizes, int n_in,
                              void* d_out, int out_size)
{
    const float* x  = (const float*)d_in[0];
    const float* b0 = (const float*)d_in[1];
    const float* b1 = (const float*)d_in[2];
    const float* b2 = (const float*)d_in[3];
    const float* a1 = (const float*)d_in[4];
    const float* a2 = (const float*)d_in[5];
    float* y = (float*)d_out;

    const int total  = NB * NK;
    const int thr    = 256;
    const int blocks = (total + thr - 1) / thr;

    biquad_pass1<<<blocks, thr>>>(x, b0, b1, b2, a1, a2);
    biquad_pass2<<<1, NB>>>(a1, a2);
    biquad_pass3<<<blocks, thr>>>(x, y, b0, b1, b2, a1, a2);
}

// round 2
// speedup vs baseline: 4.3247x; 4.3247x over previous
#include <cuda_runtime.h>

// Biquad DF2T, B=512 channels, T=48000 samples, float32.
// One block per channel. Whole channel staged in shared memory:
//   coalesced load -> per-thread chunk recurrence (zero init) ->
//   in-block Kogge-Stone state scan -> corrected sweep writing y in place ->
//   coalesced store.
// State s=(z1,z2), s' = A s + (c1 x, c2 x), A = [[-a1,1],[-a2,0]] (const per ch).

#define NB 512
#define NT 48000
#define NK 480            // chunks (= threads) per channel
#define NL 100            // samples per chunk; 480*100 = 48000, NL % 4 == 0

static_assert(NK * NL == NT, "chunking must cover T exactly");
static_assert(NL % 4 == 0, "float4 chunk walk");
static_assert(NT % (4 * NK) == 0, "coalesced float4 staging");

// dynamic smem: xs[NT] floats, then t[NK] float2 scan array
#define SMEM_BYTES (NT * 4 + NK * 8)

// one recurrence step (state update only)
#define STEP_STATE(xv)                          \
    do {                                        \
        float t_   = fmaf(c1, (xv), z2);        \
        float nz1_ = fmaf(-a1, z1, t_);         \
        z2 = fmaf(-a2, z1, c2 * (xv));          \
        z1 = nz1_;                              \
    } while (0)

__global__ void __launch_bounds__(NK, 1)
biquad_fused(const float* __restrict__ x, float* __restrict__ y,
             const float* __restrict__ b0v, const float* __restrict__ b1v,
             const float* __restrict__ b2v, const float* __restrict__ a1v,
             const float* __restrict__ a2v)
{
    extern __shared__ float xs[];
    float2* t = reinterpret_cast<float2*>(xs + NT);

    const int tid = threadIdx.x;
    const int ch  = blockIdx.x;

    const float a1 = a1v[ch], a2 = a2v[ch], b0 = b0v[ch];
    const float c1 = fmaf(-a1, b0, b1v[ch]);   // b1 - a1*b0
    const float c2 = fmaf(-a2, b0, b2v[ch]);   // b2 - a2*b0

    // ---- coalesced load: channel -> smem (12000 float4, 25 per thread) ----
    {
        const float4* __restrict__ xg4 =
            reinterpret_cast<const float4*>(x + (size_t)ch * NT);
        float4* xs4 = reinterpret_cast<float4*>(xs);
        #pragma unroll
        for (int i = 0; i < NT / 4 / NK; i++)
            xs4[tid + i * NK] = xg4[tid + i * NK];
    }
    __syncthreads();

    // ---- sweep 1: own chunk from zero state, keep end state ----
    {
        float z1 = 0.f, z2 = 0.f;
        const float4* cp = reinterpret_cast<const float4*>(xs + tid * NL);
        #pragma unroll 5
        for (int i = 0; i < NL / 4; i++) {
            float4 v = cp[i];
            STEP_STATE(v.x);
            STEP_STATE(v.y);
            STEP_STATE(v.z);
            STEP_STATE(v.w);
        }
        t[tid] = make_float2(z1, z2);
    }

    // ---- Mc = A^NL by binary powering (registers, redundant per thread) ----
    float w00, w01, w10, w11;
    {
        float m00 = -a1, m01 = 1.f, m10 = -a2, m11 = 0.f;
        float r00 = 1.f, r01 = 0.f, r10 = 0.f, r11 = 1.f;
        int e = NL;
        while (e) {
            if (e & 1) {
                float q00 = r00 * m00 + r01 * m10;
                float q01 = r00 * m01 + r01 * m11;
                float q10 = r10 * m00 + r11 * m10;
                float q11 = r10 * m01 + r11 * m11;
                r00 = q00; r01 = q01; r10 = q10; r11 = q11;
            }
            e >>= 1;
            if (e) {
                float q00 = m00 * m00 + m01 * m10;
                float q01 = m00 * m01 + m01 * m11;
                float q10 = m10 * m00 + m11 * m10;
                float q11 = m10 * m01 + m11 * m11;
                m00 = q00; m01 = q01; m10 = q10; m11 = q11;
            }
        }
        w00 = r00; w01 = r01; w10 = r10; w11 = r11;
    }
    __syncthreads();

    // ---- Kogge-Stone inclusive scan over chunk states ----
    // t[k] <- t[k] + W * t[k - off],  W = Mc^off
    for (int off = 1; off < NK; off <<= 1) {
        const bool act = (tid >= off);
        float2 prev = act ? t[tid - off] : make_float2(0.f, 0.f);
        float2 cur  = t[tid];
        __syncthreads();
        if (act) {
            cur.x = fmaf(w00, prev.x, fmaf(w01, prev.y, cur.x));
            cur.y = fmaf(w10, prev.x, fmaf(w11, prev.y, cur.y));
            t[tid] = cur;
        }
        __syncthreads();
        // W <- W * W
        float q00 = w00 * w00 + w01 * w10;
        float q01 = w00 * w01 + w01 * w11;
        float q10 = w10 * w00 + w11 * w10;
        float q11 = w10 * w01 + w11 * w11;
        w00 = q00; w01 = q01; w10 = q10; w11 = q11;
    }

    // ---- sweep 2: corrected start state, write y into smem in place ----
    {
        float z1 = 0.f, z2 = 0.f;
        if (tid > 0) { float2 s = t[tid - 1]; z1 = s.x; z2 = s.y; }
        float4* cp = reinterpret_cast<float4*>(xs + tid * NL);
        #pragma unroll 5
        for (int i = 0; i < NL / 4; i++) {
            float4 v = cp[i];
            float4 o;
            o.x = fmaf(b0, v.x, z1); STEP_STATE(v.x);
            o.y = fmaf(b0, v.y, z1); STEP_STATE(v.y);
            o.z = fmaf(b0, v.z, z1); STEP_STATE(v.z);
            o.w = fmaf(b0, v.w, z1); STEP_STATE(v.w);
            cp[i] = o;
        }
    }
    __syncthreads();

    // ---- coalesced store: smem -> y ----
    {
        float4* __restrict__ yg4 =
            reinterpret_cast<float4*>(y + (size_t)ch * NT);
        const float4* ys4 = reinterpret_cast<const float4*>(xs);
        #pragma unroll
        for (int i = 0; i < NT / 4 / NK; i++)
            yg4[tid + i * NK] = ys4[tid + i * NK];
    }
}

// ---------------------------------------------------------------------------
extern "C" void kernel_launch(void* const* d_in, const int* in_sizes, int n_in,
                              void* d_out, int out_size)
{
    const float* x  = (const float*)d_in[0];
    const float* b0 = (const float*)d_in[1];
    const float* b1 = (const float*)d_in[2];
    const float* b2 = (const float*)d_in[3];
    const float* a1 = (const float*)d_in[4];
    const float* a2 = (const float*)d_in[5];
    float* y = (float*)d_out;

    cudaFuncSetAttribute(biquad_fused,
                         cudaFuncAttributeMaxDynamicSharedMemorySize,
                         SMEM_BYTES);

    biquad_fused<<<NB, NK, SMEM_BYTES>>>(x, y, b0, b1, b2, a1, a2);
}